// round 14
// baseline (speedup 1.0000x reference)
#include <cuda_runtime.h>
#include <math.h>
#include <stdint.h>

// ---------------- problem constants ----------------
#define N_NODES 65536
#define C_IN    256
#define B_SZ    8
#define EMB_D   512
#define NET     7           // edge types
#define E_EDGES 458752
#define XA_W    288         // 256 + 7 one-hot + zero pad to 9*32 (K dim)
#define ZW      1792        // 7 * 256 output cols of dense GEMM
#define GROUPS  32
#define CPG     8
#define BK      32          // K chunk per SMEM stage
#define SST     36          // SMEM row stride (32 + 4 pad) -> conflict-free frags
#define N_CHUNKS 9
// GEMM: block tile 128m x 256n, 2-stage double buffer
#define GEMM_SMEM_BYTES ((2 * 128 * SST + 2 * 256 * SST) * 4)

// ---------------- device scratch ----------------
__device__ float g_xa[(size_t)N_NODES * XA_W];       // gn+silu output (tf32-rounded) + one-hot
__device__ float g_z [(size_t)N_NODES * ZW];         // per-node per-type conv partials
__device__ float g_h [(size_t)N_NODES * C_IN];       // intermediate h after conv1+emb
__device__ float g_wallT[(size_t)ZW * XA_W];         // W^T rows: [n=1792, k=288] tf32-rounded
__device__ float g_embout[B_SZ * C_IN];
__device__ float g_stats [B_SZ * GROUPS * 2];        // gn1 stats (from x)
__device__ float g_stats2[B_SZ * GROUPS * 2];        // gn2 stats (fused into gather)
__device__ float g_mean [B_SZ * GROUPS];
__device__ float g_istd [B_SZ * GROUPS];
__device__ int   g_count[B_SZ];
__device__ int   g_deg   [N_NODES];
__device__ int   g_start [N_NODES];
__device__ int   g_cursor[N_NODES];
__device__ int   g_packed[E_EDGES];                  // (col<<3)|type
__device__ int   g_btot[256];
__device__ int   g_boff[256];

// ---------------- tf32 round helper ----------------
__device__ __forceinline__ float tf32_rna(float x) {
    uint32_t u;
    asm("cvt.rna.tf32.f32 %0, %1;" : "=r"(u) : "f"(x));
    return __uint_as_float(u);
}

// ---------------- small utility kernels ----------------
__global__ void k_zero_all() {
    int i = blockIdx.x * blockDim.x + threadIdx.x;
    if (i < N_NODES) g_deg[i] = 0;
    if (i < B_SZ * GROUPS * 2) { g_stats[i] = 0.f; g_stats2[i] = 0.f; }
    if (i < B_SZ) g_count[i] = 0;
}

__global__ void k_hist(const int* __restrict__ batch_id) {
    __shared__ int hc[B_SZ];
    if (threadIdx.x < B_SZ) hc[threadIdx.x] = 0;
    __syncthreads();
    int stride = gridDim.x * blockDim.x;
    for (int i = blockIdx.x * blockDim.x + threadIdx.x; i < N_NODES; i += stride)
        atomicAdd(&hc[batch_id[i]], 1);
    __syncthreads();
    if (threadIdx.x < B_SZ) atomicAdd(&g_count[threadIdx.x], hc[threadIdx.x]);
}

__global__ void k_embout(const float* __restrict__ emb,
                         const float* __restrict__ emb_w,
                         const float* __restrict__ emb_b) {
    __shared__ float se[EMB_D];
    int b = blockIdx.x;
    int t = threadIdx.x;
    for (int k = t; k < EMB_D; k += 256) {
        float v = emb[b * EMB_D + k];
        se[k] = v / (1.f + expf(-v));
    }
    __syncthreads();
    float acc = emb_b[t];
    #pragma unroll 8
    for (int k = 0; k < EMB_D; k++)
        acc += se[k] * emb_w[k * C_IN + t];
    g_embout[b * C_IN + t] = acc;
}

// ---------------- CSR build ----------------
__global__ void k_deg(const int* __restrict__ erow) {
    int e = blockIdx.x * blockDim.x + threadIdx.x;
    if (e < E_EDGES) atomicAdd(&g_deg[erow[e]], 1);
}

__global__ void k_scan1() {
    __shared__ int s[256];
    int i = blockIdx.x * 256 + threadIdx.x;
    int v = g_deg[i];
    s[threadIdx.x] = v;
    __syncthreads();
    for (int off = 1; off < 256; off <<= 1) {
        int t = (threadIdx.x >= off) ? s[threadIdx.x - off] : 0;
        __syncthreads();
        s[threadIdx.x] += t;
        __syncthreads();
    }
    g_start[i] = s[threadIdx.x] - v;
    if (threadIdx.x == 255) g_btot[blockIdx.x] = s[255];
}

__global__ void k_scan2() {
    __shared__ int s[256];
    int t = threadIdx.x;
    int v = g_btot[t];
    s[t] = v;
    __syncthreads();
    for (int off = 1; off < 256; off <<= 1) {
        int u = (t >= off) ? s[t - off] : 0;
        __syncthreads();
        s[t] += u;
        __syncthreads();
    }
    g_boff[t] = s[t] - v;
}

__global__ void k_scan3() {
    int i = blockIdx.x * 256 + threadIdx.x;
    int v = g_start[i] + g_boff[i >> 8];
    g_start[i] = v;
    g_cursor[i] = v;
}

__global__ void k_fill(const int* __restrict__ erow,
                       const int* __restrict__ ecol,
                       const int* __restrict__ etype) {
    int e = blockIdx.x * blockDim.x + threadIdx.x;
    if (e < E_EDGES) {
        int pos = atomicAdd(&g_cursor[erow[e]], 1);
        g_packed[pos] = (ecol[e] << 3) | etype[e];
    }
}

// ---------------- group-norm stats (block 1 only: reads x) ----------------
__global__ void k_stats(const float* __restrict__ ext,
                        const int* __restrict__ batch_id) {
    int c = threadIdx.x;
    int r0 = blockIdx.x * 128;
    int g = c >> 3;
    const float* src = ext;
    int b_first = batch_id[r0];
    if (b_first == batch_id[r0 + 127]) {
        float s1 = 0.f, s2 = 0.f;
        #pragma unroll 8
        for (int r = r0; r < r0 + 128; ++r) {
            float v = src[(size_t)r * C_IN + c];
            s1 += v;
            s2 += v * v;
        }
        atomicAdd(&g_stats[(b_first * GROUPS + g) * 2 + 0], s1);
        atomicAdd(&g_stats[(b_first * GROUPS + g) * 2 + 1], s2);
        return;
    }
    float s1 = 0.f, s2 = 0.f;
    int cb = b_first;
    for (int r = r0; r < r0 + 128; ++r) {
        int b = batch_id[r];
        if (b != cb) {
            atomicAdd(&g_stats[(cb * GROUPS + g) * 2 + 0], s1);
            atomicAdd(&g_stats[(cb * GROUPS + g) * 2 + 1], s2);
            s1 = 0.f; s2 = 0.f; cb = b;
        }
        float v = src[(size_t)r * C_IN + c];
        s1 += v;
        s2 += v * v;
    }
    atomicAdd(&g_stats[(cb * GROUPS + g) * 2 + 0], s1);
    atomicAdd(&g_stats[(cb * GROUPS + g) * 2 + 1], s2);
}

__global__ void k_finalize(int which) {
    int t = threadIdx.x;
    if (t >= B_SZ * GROUPS) return;
    const float* st = which ? g_stats2 : g_stats;
    int b = t / GROUPS;
    float n = (float)g_count[b] * (float)CPG;
    float ic = 1.f / (n + 1e-5f);
    float s1 = st[t * 2 + 0];
    float s2 = st[t * 2 + 1];
    float m = s1 * ic;
    float var = (s2 - 2.f * m * s1 + n * m * m) * ic;
    g_mean[t] = m;
    g_istd[t] = rsqrtf(fmaxf(var, 0.f) + 1e-5f);
}

// 4 rows per block, 256 threads; writes tf32-rounded values + one-hot + pad
__global__ void k_apply(const float* __restrict__ ext, int use_h,
                        const float* __restrict__ gnw,
                        const float* __restrict__ gnb,
                        const int* __restrict__ node_type,
                        const int* __restrict__ batch_id) {
    int c = threadIdx.x;
    int g = c >> 3;
    float w = gnw[c], bb = gnb[c];
    int i0 = blockIdx.x * 4;
    #pragma unroll
    for (int r = 0; r < 4; r++) {
        int i = i0 + r;
        int b = batch_id[i];
        float m = g_mean[b * GROUPS + g];
        float is = g_istd[b * GROUPS + g];
        float v = use_h ? g_h[(size_t)i * C_IN + c] : ext[(size_t)i * C_IN + c];
        float t = (v - m) * is * w + bb;
        float sv = t / (1.f + expf(-t));
        g_xa[(size_t)i * XA_W + c] = tf32_rna(sv);
        if (c < 32) {
            int nt = node_type[i];
            g_xa[(size_t)i * XA_W + 256 + c] = (c < 7 && nt == c) ? 1.f : 0.f;
        }
    }
}

// ---------------- weight transpose (coalesced, 32x32 SMEM tiles) -------------
// wallT[n = t*256 + j][k = kk] = conv_w[(t*263 + kk)*256 + j], kk>=263 -> 0
// grid: 7 types * 9 k-tiles * 8 j-tiles = 504 blocks, block (32,8)
__global__ void k_wallT(const float* __restrict__ conv_w) {
    __shared__ float tile[32][33];
    int b = blockIdx.x;
    int t = b / 72;
    int rem = b - t * 72;
    int kt = rem >> 3;           // 0..8
    int jt = rem & 7;            // 0..7
    int tx = threadIdx.x;        // 0..31
    int ty = threadIdx.y;        // 0..7
    #pragma unroll
    for (int i = 0; i < 4; i++) {
        int kk = kt * 32 + ty + i * 8;
        float v = (kk < 263) ? conv_w[(size_t)(t * 263 + kk) * 256 + jt * 32 + tx] : 0.f;
        tile[ty + i * 8][tx] = tf32_rna(v);
    }
    __syncthreads();
    #pragma unroll
    for (int i = 0; i < 4; i++) {
        int j = jt * 32 + ty + i * 8;
        g_wallT[(size_t)(t * 256 + j) * XA_W + kt * 32 + tx] = tile[tx][ty + i * 8];
    }
}

// ---------------- mma.sync tf32 GEMM ----------------
__device__ __forceinline__ void mma_1688(float& c0, float& c1, float& c2, float& c3,
                                         uint32_t a0, uint32_t a1, uint32_t a2, uint32_t a3,
                                         uint32_t b0, uint32_t b1) {
    asm volatile(
        "mma.sync.aligned.m16n8k8.row.col.f32.tf32.tf32.f32 "
        "{%0,%1,%2,%3}, {%4,%5,%6,%7}, {%8,%9}, {%0,%1,%2,%3};"
        : "+f"(c0), "+f"(c1), "+f"(c2), "+f"(c3)
        : "r"(a0), "r"(a1), "r"(a2), "r"(a3), "r"(b0), "r"(b1));
}

#define CP_ASYNC16(dst, src) \
    asm volatile("cp.async.ca.shared.global [%0], [%1], 16;" :: "r"(dst), "l"(src) : "memory")

// g_z[65536,1792] = g_xa[65536,288] @ g_wallT[1792,288]^T
// block tile 128m x 256n, 8 warps (warp tile 64x64), K in 9 chunks of 32,
// 2-stage cp.async double buffering.
__global__ void __launch_bounds__(256) k_gemm_mma() {
    extern __shared__ uint32_t dsm[];
    uint32_t* sA = dsm;                       // 2 stages x 128 x SST
    uint32_t* sB = dsm + 2 * 128 * SST;       // 2 stages x 256 x SST

    int tid = threadIdx.x;
    int lane = tid & 31;
    int wid = tid >> 5;
    int bn = blockIdx.x * 256;
    int bm = blockIdx.y * 128;
    int wm = (wid & 1) * 64;
    int wn = (wid >> 1) * 64;
    int grp = lane >> 2;
    int tig = lane & 3;

    float acc[4][8][4];
    #pragma unroll
    for (int mt = 0; mt < 4; mt++)
        #pragma unroll
        for (int nt = 0; nt < 8; nt++)
            #pragma unroll
            for (int q = 0; q < 4; q++) acc[mt][nt][q] = 0.f;

    const float* gA = g_xa    + (size_t)bm * XA_W;
    const float* gB = g_wallT + (size_t)bn * XA_W;
    int lr = tid >> 3;
    int lc = (tid & 7) * 4;

    uint32_t sA_base = (uint32_t)__cvta_generic_to_shared(sA);
    uint32_t sB_base = (uint32_t)__cvta_generic_to_shared(sB);

    auto issue = [&](int c, int buf) {
        uint32_t aoff = (uint32_t)(buf * 128 * SST) * 4;
        uint32_t boff = (uint32_t)(buf * 256 * SST) * 4;
        #pragma unroll
        for (int i = 0; i < 4; i++) {
            int row = lr + i * 32;
            CP_ASYNC16(sA_base + aoff + (row * SST + lc) * 4,
                       gA + (size_t)row * XA_W + c * BK + lc);
        }
        #pragma unroll
        for (int i = 0; i < 8; i++) {
            int row = lr + i * 32;
            CP_ASYNC16(sB_base + boff + (row * SST + lc) * 4,
                       gB + (size_t)row * XA_W + c * BK + lc);
        }
        asm volatile("cp.async.commit_group;" ::: "memory");
    };

    issue(0, 0);

    for (int c = 0; c < N_CHUNKS; c++) {
        int buf = c & 1;
        if (c + 1 < N_CHUNKS) {
            issue(c + 1, buf ^ 1);
            asm volatile("cp.async.wait_group 1;" ::: "memory");
        } else {
            asm volatile("cp.async.wait_group 0;" ::: "memory");
        }
        __syncthreads();

        const uint32_t* cA = sA + buf * 128 * SST;
        const uint32_t* cB = sB + buf * 256 * SST;
        #pragma unroll
        for (int kk = 0; kk < 4; kk++) {
            int k = kk * 8;
            uint32_t af[4][4];
            uint32_t bf[8][2];
            #pragma unroll
            for (int mt = 0; mt < 4; mt++) {
                int r0 = wm + mt * 16 + grp;
                af[mt][0] = cA[r0 * SST + k + tig];
                af[mt][1] = cA[(r0 + 8) * SST + k + tig];
                af[mt][2] = cA[r0 * SST + k + tig + 4];
                af[mt][3] = cA[(r0 + 8) * SST + k + tig + 4];
            }
            #pragma unroll
            for (int nt = 0; nt < 8; nt++) {
                int n0 = wn + nt * 8 + grp;
                bf[nt][0] = cB[n0 * SST + k + tig];
                bf[nt][1] = cB[n0 * SST + k + tig + 4];
            }
            #pragma unroll
            for (int mt = 0; mt < 4; mt++)
                #pragma unroll
                for (int nt = 0; nt < 8; nt++)
                    mma_1688(acc[mt][nt][0], acc[mt][nt][1], acc[mt][nt][2], acc[mt][nt][3],
                             af[mt][0], af[mt][1], af[mt][2], af[mt][3],
                             bf[nt][0], bf[nt][1]);
        }
        __syncthreads();
    }

    // epilogue (plain stores — z benefits from L2 residency in the gather)
    #pragma unroll
    for (int mt = 0; mt < 4; mt++) {
        int r0 = bm + wm + mt * 16 + grp;
        #pragma unroll
        for (int nt = 0; nt < 8; nt++) {
            int cc = bn + wn + nt * 8 + tig * 2;
            *(float2*)(g_z + (size_t)r0 * ZW + cc)       = make_float2(acc[mt][nt][0], acc[mt][nt][1]);
            *(float2*)(g_z + (size_t)(r0 + 8) * ZW + cc) = make_float2(acc[mt][nt][2], acc[mt][nt][3]);
        }
    }
}

// ---------------- CSR gather-sum of z rows (2-deep pipelined) ----------------
// mode 0: init = embout[batch], dst = g_h, ALSO accumulates gn2 stats (fused).
// mode 1: init = x (skip),      dst = out.
__global__ void k_gather(const int* __restrict__ batch_id,
                         const float* __restrict__ x,
                         float* __restrict__ out, int mode) {
    int gw = (blockIdx.x * blockDim.x + threadIdx.x) >> 5;
    if (gw >= N_NODES) return;
    int lane = threadIdx.x & 31;
    int bid = 0;
    const float4* ip;
    if (mode == 0) {
        bid = batch_id[gw];
        ip = (const float4*)(g_embout + (size_t)bid * C_IN + lane * 8);
    } else {
        ip = (const float4*)(x + (size_t)gw * C_IN + lane * 8);
    }
    float4 v0 = ip[0], v1 = ip[1];
    float acc[8] = {v0.x, v0.y, v0.z, v0.w, v1.x, v1.y, v1.z, v1.w};
    int s = g_start[gw];
    int d = g_deg[gw];

    float4 ca, cb;
    if (d > 0) {
        int p = g_packed[s];
        const float4* zp = (const float4*)(g_z + (size_t)(p >> 3) * ZW + (p & 7) * C_IN + lane * 8);
        ca = zp[0]; cb = zp[1];
    }
    for (int e = 0; e < d; e++) {
        float4 na, nb;
        if (e + 1 < d) {
            int p = g_packed[s + e + 1];
            const float4* zp = (const float4*)(g_z + (size_t)(p >> 3) * ZW + (p & 7) * C_IN + lane * 8);
            na = zp[0]; nb = zp[1];
        }
        acc[0] += ca.x; acc[1] += ca.y; acc[2] += ca.z; acc[3] += ca.w;
        acc[4] += cb.x; acc[5] += cb.y; acc[6] += cb.z; acc[7] += cb.w;
        if (e + 1 < d) { ca = na; cb = nb; }
    }
    float* op = (mode == 0) ? (g_h + (size_t)gw * C_IN + lane * 8)
                            : (out + (size_t)gw * C_IN + lane * 8);
    *(float4*)(op)     = make_float4(acc[0], acc[1], acc[2], acc[3]);
    *(float4*)(op + 4) = make_float4(acc[4], acc[5], acc[6], acc[7]);

    if (mode == 0) {
        // fused gn2 stats: lane's 8 channels == one group (group == lane)
        float s1 = 0.f, s2 = 0.f;
        #pragma unroll
        for (int q = 0; q < 8; q++) { s1 += acc[q]; s2 += acc[q] * acc[q]; }
        atomicAdd(&g_stats2[(bid * GROUPS + lane) * 2 + 0], s1);
        atomicAdd(&g_stats2[(bid * GROUPS + lane) * 2 + 1], s2);
    }
}

// ---------------- launch ----------------
extern "C" void kernel_launch(void* const* d_in, const int* in_sizes, int n_in,
                              void* d_out, int out_size) {
    const float* x        = (const float*)d_in[0];
    const float* emb      = (const float*)d_in[1];
    const int*   batch_id = (const int*)  d_in[2];
    const int*   eidx     = (const int*)  d_in[3];
    const int*   etype    = (const int*)  d_in[4];
    const int*   ntype    = (const int*)  d_in[5];
    const float* gn1_w    = (const float*)d_in[6];
    const float* gn1_b    = (const float*)d_in[7];
    const float* conv1_w  = (const float*)d_in[8];
    const float* emb_w    = (const float*)d_in[9];
    const float* emb_b    = (const float*)d_in[10];
    const float* gn2_w    = (const float*)d_in[11];
    const float* gn2_b    = (const float*)d_in[12];
    const float* conv2_w  = (const float*)d_in[13];
    float* out = (float*)d_out;

    const int* erow = eidx;
    const int* ecol = eidx + E_EDGES;

    cudaFuncSetAttribute(k_gemm_mma, cudaFuncAttributeMaxDynamicSharedMemorySize,
                         GEMM_SMEM_BYTES);

    // init + CSR (edge structure is the same for both convs)
    k_zero_all<<<256, 256>>>();
    k_embout<<<B_SZ, 256>>>(emb, emb_w, emb_b);
    k_hist<<<64, 256>>>(batch_id);
    k_deg<<<E_EDGES / 1024, 1024>>>(erow);
    k_scan1<<<256, 256>>>();
    k_scan2<<<1, 256>>>();
    k_scan3<<<256, 256>>>();
    k_fill<<<E_EDGES / 1024, 1024>>>(erow, ecol, etype);

    dim3 gemm_grid(ZW / 256, N_NODES / 128);
    dim3 wt_block(32, 8);

    // ---- block 1: gn1 + silu + conv1 + emb add (+fused gn2 stats) ----
    k_stats<<<512, 256>>>(x, batch_id);
    k_finalize<<<1, 256>>>(0);
    k_apply<<<N_NODES / 4, 256>>>(x, 0, gn1_w, gn1_b, ntype, batch_id);
    k_wallT<<<504, wt_block>>>(conv1_w);
    k_gemm_mma<<<gemm_grid, 256, GEMM_SMEM_BYTES>>>();
    k_gather<<<(N_NODES * 32) / 256, 256>>>(batch_id, x, out, 0);  // -> g_h (+emb) + stats2

    // ---- block 2: gn2 + silu + conv2 + skip ----
    k_finalize<<<1, 256>>>(1);
    k_apply<<<N_NODES / 4, 256>>>(x, 1, gn2_w, gn2_b, ntype, batch_id);
    k_wallT<<<504, wt_block>>>(conv2_w);
    k_gemm_mma<<<gemm_grid, 256, GEMM_SMEM_BYTES>>>();
    k_gather<<<(N_NODES * 32) / 256, 256>>>(batch_id, x, out, 1);  // -> out (+x)
}

// round 15
// speedup vs baseline: 1.7915x; 1.7915x over previous
#include <cuda_runtime.h>
#include <math.h>
#include <stdint.h>

// ---------------- problem constants ----------------
#define N_NODES 65536
#define C_IN    256
#define B_SZ    8
#define EMB_D   512
#define NET     7           // edge types
#define E_EDGES 458752
#define XA_W    288         // 256 + 7 one-hot + zero pad to 9*32 (K dim)
#define ZW      1792        // 7 * 256 output cols of dense GEMM
#define GROUPS  32
#define CPG     8
#define BK      32          // K chunk per SMEM stage
#define SST     36          // SMEM row stride (32 + 4 pad) -> conflict-free frags
#define N_CHUNKS 9
// GEMM v2: block tile 128m x 256n, 2-stage double buffer
#define GEMM_SMEM_BYTES ((2 * 128 * SST + 2 * 256 * SST) * 4)

// ---------------- device scratch ----------------
__device__ float g_xa[(size_t)N_NODES * XA_W];       // gn+silu output (tf32-rounded) + one-hot
__device__ float g_z [(size_t)N_NODES * ZW];         // per-node per-type conv partials
__device__ float g_h [(size_t)N_NODES * C_IN];       // intermediate h after conv1+emb
__device__ float g_wallT[(size_t)ZW * XA_W];         // W^T rows: [n=1792, k=288] tf32-rounded
__device__ float g_embout[B_SZ * C_IN];
__device__ float g_stats[B_SZ * GROUPS * 2];
__device__ float g_mean [B_SZ * GROUPS];
__device__ float g_istd [B_SZ * GROUPS];
__device__ int   g_count[B_SZ];
__device__ int   g_deg   [N_NODES];
__device__ int   g_start [N_NODES];
__device__ int   g_cursor[N_NODES];
__device__ int   g_packed[E_EDGES];                  // (col<<3)|type
__device__ int   g_btot[256];
__device__ int   g_boff[256];

// ---------------- tf32 round helper ----------------
__device__ __forceinline__ float tf32_rna(float x) {
    uint32_t u;
    asm("cvt.rna.tf32.f32 %0, %1;" : "=r"(u) : "f"(x));
    return __uint_as_float(u);
}

// ---------------- small utility kernels ----------------
__global__ void k_zero_all() {
    int i = blockIdx.x * blockDim.x + threadIdx.x;
    if (i < N_NODES) g_deg[i] = 0;
    if (i < B_SZ * GROUPS * 2) g_stats[i] = 0.f;
    if (i < B_SZ) g_count[i] = 0;
}

__global__ void k_zero_stats() {
    int i = blockIdx.x * blockDim.x + threadIdx.x;
    if (i < B_SZ * GROUPS * 2) g_stats[i] = 0.f;
}

__global__ void k_hist(const int* __restrict__ batch_id) {
    __shared__ int hc[B_SZ];
    if (threadIdx.x < B_SZ) hc[threadIdx.x] = 0;
    __syncthreads();
    int stride = gridDim.x * blockDim.x;
    for (int i = blockIdx.x * blockDim.x + threadIdx.x; i < N_NODES; i += stride)
        atomicAdd(&hc[batch_id[i]], 1);
    __syncthreads();
    if (threadIdx.x < B_SZ) atomicAdd(&g_count[threadIdx.x], hc[threadIdx.x]);
}

__global__ void k_embout(const float* __restrict__ emb,
                         const float* __restrict__ emb_w,
                         const float* __restrict__ emb_b) {
    __shared__ float se[EMB_D];
    int b = blockIdx.x;
    int t = threadIdx.x;
    for (int k = t; k < EMB_D; k += 256) {
        float v = emb[b * EMB_D + k];
        se[k] = v / (1.f + expf(-v));
    }
    __syncthreads();
    float acc = emb_b[t];
    #pragma unroll 8
    for (int k = 0; k < EMB_D; k++)
        acc += se[k] * emb_w[k * C_IN + t];
    g_embout[b * C_IN + t] = acc;
}

// ---------------- CSR build ----------------
__global__ void k_deg(const int* __restrict__ erow) {
    int e = blockIdx.x * blockDim.x + threadIdx.x;
    if (e < E_EDGES) atomicAdd(&g_deg[erow[e]], 1);
}

__global__ void k_scan1() {
    __shared__ int s[256];
    int i = blockIdx.x * 256 + threadIdx.x;
    int v = g_deg[i];
    s[threadIdx.x] = v;
    __syncthreads();
    for (int off = 1; off < 256; off <<= 1) {
        int t = (threadIdx.x >= off) ? s[threadIdx.x - off] : 0;
        __syncthreads();
        s[threadIdx.x] += t;
        __syncthreads();
    }
    g_start[i] = s[threadIdx.x] - v;
    if (threadIdx.x == 255) g_btot[blockIdx.x] = s[255];
}

__global__ void k_scan2() {
    __shared__ int s[256];
    int t = threadIdx.x;
    int v = g_btot[t];
    s[t] = v;
    __syncthreads();
    for (int off = 1; off < 256; off <<= 1) {
        int u = (t >= off) ? s[t - off] : 0;
        __syncthreads();
        s[t] += u;
        __syncthreads();
    }
    g_boff[t] = s[t] - v;
}

__global__ void k_scan3() {
    int i = blockIdx.x * 256 + threadIdx.x;
    int v = g_start[i] + g_boff[i >> 8];
    g_start[i] = v;
    g_cursor[i] = v;
}

__global__ void k_fill(const int* __restrict__ erow,
                       const int* __restrict__ ecol,
                       const int* __restrict__ etype) {
    int e = blockIdx.x * blockDim.x + threadIdx.x;
    if (e < E_EDGES) {
        int pos = atomicAdd(&g_cursor[erow[e]], 1);
        g_packed[pos] = (ecol[e] << 3) | etype[e];
    }
}

// ---------------- group-norm ----------------
__global__ void k_stats(const float* __restrict__ ext, int use_h,
                        const int* __restrict__ batch_id) {
    int c = threadIdx.x;
    int r0 = blockIdx.x * 128;
    int g = c >> 3;
    const float* src = use_h ? (const float*)g_h : ext;
    int b_first = batch_id[r0];
    if (b_first == batch_id[r0 + 127]) {
        // fast path: whole tile in one batch — unrolled, branch-free
        float s1 = 0.f, s2 = 0.f;
        #pragma unroll 8
        for (int r = r0; r < r0 + 128; ++r) {
            float v = src[(size_t)r * C_IN + c];
            s1 += v;
            s2 += v * v;
        }
        atomicAdd(&g_stats[(b_first * GROUPS + g) * 2 + 0], s1);
        atomicAdd(&g_stats[(b_first * GROUPS + g) * 2 + 1], s2);
        return;
    }
    float s1 = 0.f, s2 = 0.f;
    int cb = b_first;
    for (int r = r0; r < r0 + 128; ++r) {
        int b = batch_id[r];
        if (b != cb) {
            atomicAdd(&g_stats[(cb * GROUPS + g) * 2 + 0], s1);
            atomicAdd(&g_stats[(cb * GROUPS + g) * 2 + 1], s2);
            s1 = 0.f; s2 = 0.f; cb = b;
        }
        float v = src[(size_t)r * C_IN + c];
        s1 += v;
        s2 += v * v;
    }
    atomicAdd(&g_stats[(cb * GROUPS + g) * 2 + 0], s1);
    atomicAdd(&g_stats[(cb * GROUPS + g) * 2 + 1], s2);
}

__global__ void k_finalize() {
    int t = threadIdx.x;
    if (t >= B_SZ * GROUPS) return;
    int b = t / GROUPS;
    float n = (float)g_count[b] * (float)CPG;
    float ic = 1.f / (n + 1e-5f);
    float s1 = g_stats[t * 2 + 0];
    float s2 = g_stats[t * 2 + 1];
    float m = s1 * ic;
    float var = (s2 - 2.f * m * s1 + n * m * m) * ic;
    g_mean[t] = m;
    g_istd[t] = rsqrtf(fmaxf(var, 0.f) + 1e-5f);
}

// 4 rows per block, 256 threads; writes tf32-rounded values + one-hot + pad
__global__ void k_apply(const float* __restrict__ ext, int use_h,
                        const float* __restrict__ gnw,
                        const float* __restrict__ gnb,
                        const int* __restrict__ node_type,
                        const int* __restrict__ batch_id) {
    int c = threadIdx.x;
    int g = c >> 3;
    float w = gnw[c], bb = gnb[c];
    int i0 = blockIdx.x * 4;
    #pragma unroll
    for (int r = 0; r < 4; r++) {
        int i = i0 + r;
        int b = batch_id[i];
        float m = g_mean[b * GROUPS + g];
        float is = g_istd[b * GROUPS + g];
        float v = use_h ? g_h[(size_t)i * C_IN + c] : ext[(size_t)i * C_IN + c];
        float t = (v - m) * is * w + bb;
        float sv = t / (1.f + expf(-t));
        g_xa[(size_t)i * XA_W + c] = tf32_rna(sv);
        if (c < 32) {
            int nt = node_type[i];
            g_xa[(size_t)i * XA_W + 256 + c] = (c < 7 && nt == c) ? 1.f : 0.f;
        }
    }
}

// ---------------- weight transpose: wallT[n=t*256+j][k] = conv_w[t*263+k][j] ----------------
__global__ void k_wallT(const float* __restrict__ conv_w) {
    int idx = blockIdx.x * blockDim.x + threadIdx.x;
    if (idx >= ZW * XA_W) return;
    int n = idx / XA_W;
    int k = idx - n * XA_W;
    int t = n >> 8;
    int j = n & 255;
    float v = (k < 263) ? conv_w[(size_t)(t * 263 + k) * 256 + j] : 0.f;
    g_wallT[idx] = tf32_rna(v);
}

// ---------------- mma.sync tf32 GEMM ----------------
__device__ __forceinline__ void mma_1688(float& c0, float& c1, float& c2, float& c3,
                                         uint32_t a0, uint32_t a1, uint32_t a2, uint32_t a3,
                                         uint32_t b0, uint32_t b1) {
    asm volatile(
        "mma.sync.aligned.m16n8k8.row.col.f32.tf32.tf32.f32 "
        "{%0,%1,%2,%3}, {%4,%5,%6,%7}, {%8,%9}, {%0,%1,%2,%3};"
        : "+f"(c0), "+f"(c1), "+f"(c2), "+f"(c3)
        : "r"(a0), "r"(a1), "r"(a2), "r"(a3), "r"(b0), "r"(b1));
}

#define CP_ASYNC16(dst, src) \
    asm volatile("cp.async.ca.shared.global [%0], [%1], 16;" :: "r"(dst), "l"(src) : "memory")

// g_z[65536,1792] = g_xa[65536,288] @ g_wallT[1792,288]^T
// block tile 128m x 256n, 8 warps (warp tile 64x64), K in 9 chunks of 32,
// 2-stage cp.async double buffering.
// grid: x = n-tile (7), y = m-tile (512)
__global__ void __launch_bounds__(256) k_gemm_mma() {
    extern __shared__ uint32_t dsm[];
    uint32_t* sA = dsm;                       // 2 stages x 128 x SST
    uint32_t* sB = dsm + 2 * 128 * SST;       // 2 stages x 256 x SST

    int tid = threadIdx.x;
    int lane = tid & 31;
    int wid = tid >> 5;
    int bn = blockIdx.x * 256;
    int bm = blockIdx.y * 128;
    int wm = (wid & 1) * 64;     // warp row offset (0,64)
    int wn = (wid >> 1) * 64;    // warp col offset (0,64,128,192)
    int grp = lane >> 2;         // groupID
    int tig = lane & 3;          // threadID_in_group

    float acc[4][8][4];
    #pragma unroll
    for (int mt = 0; mt < 4; mt++)
        #pragma unroll
        for (int nt = 0; nt < 8; nt++)
            #pragma unroll
            for (int q = 0; q < 4; q++) acc[mt][nt][q] = 0.f;

    const float* gA = g_xa    + (size_t)bm * XA_W;
    const float* gB = g_wallT + (size_t)bn * XA_W;
    int lr = tid >> 3;           // load row base (0..31)
    int lc = (tid & 7) * 4;      // load col (float4)

    uint32_t sA_base = (uint32_t)__cvta_generic_to_shared(sA);
    uint32_t sB_base = (uint32_t)__cvta_generic_to_shared(sB);

    auto issue = [&](int c, int buf) {
        uint32_t aoff = (uint32_t)(buf * 128 * SST) * 4;
        uint32_t boff = (uint32_t)(buf * 256 * SST) * 4;
        #pragma unroll
        for (int i = 0; i < 4; i++) {
            int row = lr + i * 32;
            CP_ASYNC16(sA_base + aoff + (row * SST + lc) * 4,
                       gA + (size_t)row * XA_W + c * BK + lc);
        }
        #pragma unroll
        for (int i = 0; i < 8; i++) {
            int row = lr + i * 32;
            CP_ASYNC16(sB_base + boff + (row * SST + lc) * 4,
                       gB + (size_t)row * XA_W + c * BK + lc);
        }
        asm volatile("cp.async.commit_group;" ::: "memory");
    };

    issue(0, 0);

    for (int c = 0; c < N_CHUNKS; c++) {
        int buf = c & 1;
        if (c + 1 < N_CHUNKS) {
            issue(c + 1, buf ^ 1);
            asm volatile("cp.async.wait_group 1;" ::: "memory");
        } else {
            asm volatile("cp.async.wait_group 0;" ::: "memory");
        }
        __syncthreads();

        const uint32_t* cA = sA + buf * 128 * SST;
        const uint32_t* cB = sB + buf * 256 * SST;
        #pragma unroll
        for (int kk = 0; kk < 4; kk++) {
            int k = kk * 8;
            uint32_t af[4][4];
            uint32_t bf[8][2];
            #pragma unroll
            for (int mt = 0; mt < 4; mt++) {
                int r0 = wm + mt * 16 + grp;
                af[mt][0] = cA[r0 * SST + k + tig];
                af[mt][1] = cA[(r0 + 8) * SST + k + tig];
                af[mt][2] = cA[r0 * SST + k + tig + 4];
                af[mt][3] = cA[(r0 + 8) * SST + k + tig + 4];
            }
            #pragma unroll
            for (int nt = 0; nt < 8; nt++) {
                int n0 = wn + nt * 8 + grp;
                bf[nt][0] = cB[n0 * SST + k + tig];
                bf[nt][1] = cB[n0 * SST + k + tig + 4];
            }
            #pragma unroll
            for (int mt = 0; mt < 4; mt++)
                #pragma unroll
                for (int nt = 0; nt < 8; nt++)
                    mma_1688(acc[mt][nt][0], acc[mt][nt][1], acc[mt][nt][2], acc[mt][nt][3],
                             af[mt][0], af[mt][1], af[mt][2], af[mt][3],
                             bf[nt][0], bf[nt][1]);
        }
        __syncthreads();
    }

    // epilogue
    #pragma unroll
    for (int mt = 0; mt < 4; mt++) {
        int r0 = bm + wm + mt * 16 + grp;
        #pragma unroll
        for (int nt = 0; nt < 8; nt++) {
            int cc = bn + wn + nt * 8 + tig * 2;
            *(float2*)(g_z + (size_t)r0 * ZW + cc)       = make_float2(acc[mt][nt][0], acc[mt][nt][1]);
            *(float2*)(g_z + (size_t)(r0 + 8) * ZW + cc) = make_float2(acc[mt][nt][2], acc[mt][nt][3]);
        }
    }
}

// ---------------- CSR gather-sum of z rows (2-deep pipelined) ----------------
__global__ void k_gather(const int* __restrict__ batch_id,
                         const float* __restrict__ x,
                         float* __restrict__ out, int mode) {
    int gw = (blockIdx.x * blockDim.x + threadIdx.x) >> 5;
    if (gw >= N_NODES) return;
    int lane = threadIdx.x & 31;
    const float4* ip;
    if (mode == 0)
        ip = (const float4*)(g_embout + (size_t)batch_id[gw] * C_IN + lane * 8);
    else
        ip = (const float4*)(x + (size_t)gw * C_IN + lane * 8);
    float4 v0 = ip[0], v1 = ip[1];
    float acc[8] = {v0.x, v0.y, v0.z, v0.w, v1.x, v1.y, v1.z, v1.w};
    int s = g_start[gw];
    int d = g_deg[gw];

    float4 ca, cb;
    if (d > 0) {
        int p = g_packed[s];
        const float4* zp = (const float4*)(g_z + (size_t)(p >> 3) * ZW + (p & 7) * C_IN + lane * 8);
        ca = zp[0]; cb = zp[1];
    }
    for (int e = 0; e < d; e++) {
        float4 na, nb;
        if (e + 1 < d) {
            int p = g_packed[s + e + 1];
            const float4* zp = (const float4*)(g_z + (size_t)(p >> 3) * ZW + (p & 7) * C_IN + lane * 8);
            na = zp[0]; nb = zp[1];
        }
        acc[0] += ca.x; acc[1] += ca.y; acc[2] += ca.z; acc[3] += ca.w;
        acc[4] += cb.x; acc[5] += cb.y; acc[6] += cb.z; acc[7] += cb.w;
        if (e + 1 < d) { ca = na; cb = nb; }
    }
    float* op = (mode == 0) ? (g_h + (size_t)gw * C_IN + lane * 8)
                            : (out + (size_t)gw * C_IN + lane * 8);
    *(float4*)(op)     = make_float4(acc[0], acc[1], acc[2], acc[3]);
    *(float4*)(op + 4) = make_float4(acc[4], acc[5], acc[6], acc[7]);
}

// ---------------- launch ----------------
extern "C" void kernel_launch(void* const* d_in, const int* in_sizes, int n_in,
                              void* d_out, int out_size) {
    const float* x        = (const float*)d_in[0];
    const float* emb      = (const float*)d_in[1];
    const int*   batch_id = (const int*)  d_in[2];
    const int*   eidx     = (const int*)  d_in[3];
    const int*   etype    = (const int*)  d_in[4];
    const int*   ntype    = (const int*)  d_in[5];
    const float* gn1_w    = (const float*)d_in[6];
    const float* gn1_b    = (const float*)d_in[7];
    const float* conv1_w  = (const float*)d_in[8];
    const float* emb_w    = (const float*)d_in[9];
    const float* emb_b    = (const float*)d_in[10];
    const float* gn2_w    = (const float*)d_in[11];
    const float* gn2_b    = (const float*)d_in[12];
    const float* conv2_w  = (const float*)d_in[13];
    float* out = (float*)d_out;

    const int* erow = eidx;
    const int* ecol = eidx + E_EDGES;

    cudaFuncSetAttribute(k_gemm_mma, cudaFuncAttributeMaxDynamicSharedMemorySize,
                         GEMM_SMEM_BYTES);

    // init + CSR (edge structure is the same for both convs)
    k_zero_all<<<256, 256>>>();
    k_embout<<<B_SZ, 256>>>(emb, emb_w, emb_b);
    k_hist<<<64, 256>>>(batch_id);
    k_deg<<<E_EDGES / 1024, 1024>>>(erow);
    k_scan1<<<256, 256>>>();
    k_scan2<<<1, 256>>>();
    k_scan3<<<256, 256>>>();
    k_fill<<<E_EDGES / 1024, 1024>>>(erow, ecol, etype);

    dim3 gemm_grid(ZW / 256, N_NODES / 128);

    // ---- block 1: gn1 + silu + conv1 + emb add ----
    k_stats<<<512, 256>>>(x, 0, batch_id);
    k_finalize<<<1, 256>>>();
    k_apply<<<N_NODES / 4, 256>>>(x, 0, gn1_w, gn1_b, ntype, batch_id);
    k_wallT<<<(ZW * XA_W + 255) / 256, 256>>>(conv1_w);
    k_gemm_mma<<<gemm_grid, 256, GEMM_SMEM_BYTES>>>();
    k_gather<<<(N_NODES * 32) / 256, 256>>>(batch_id, x, out, 0);  // -> g_h (+emb)

    // ---- block 2: gn2 + silu + conv2 + skip ----
    k_zero_stats<<<2, 256>>>();
    k_stats<<<512, 256>>>(x, 1, batch_id);
    k_finalize<<<1, 256>>>();
    k_apply<<<N_NODES / 4, 256>>>(x, 1, gn2_w, gn2_b, ntype, batch_id);
    k_wallT<<<(ZW * XA_W + 255) / 256, 256>>>(conv2_w);
    k_gemm_mma<<<gemm_grid, 256, GEMM_SMEM_BYTES>>>();
    k_gather<<<(N_NODES * 32) / 256, 256>>>(batch_id, x, out, 1);  // -> out (+x)
}